// round 1
// baseline (speedup 1.0000x reference)
#include <cuda_runtime.h>
#include <math.h>

#define NN 320
#define HN 160
#define NPIX (NN*NN)
#define NVEC (4*NPIX)        // 409600 complex
#define NIMG 64              // 4 shots * 16 coils
#define RHO_F 0.1f
#define EPS_F 1e-12f

// ---------------- device globals (scratch) ----------------
__device__ float2 d_scr[NIMG*NPIX];   // 52.4 MB k-space / hybrid scratch
__device__ float2 d_x[NVEC];
__device__ float2 d_r[NVEC];
__device__ float2 d_p[NVEC];
__device__ float2 d_Ap[NVEC];
__device__ float2 d_W[NN];            // twiddle table exp(-2*pi*i*k/320)
__device__ float  d_part[2048];       // reduction partials
__device__ float  d_sc[4];            // 0: rs, 1: alpha, 2: beta

// ---------------- complex helpers ----------------
__device__ __forceinline__ float2 cad(float2 a, float2 b){ return make_float2(a.x+b.x, a.y+b.y); }
__device__ __forceinline__ float2 csb(float2 a, float2 b){ return make_float2(a.x-b.x, a.y-b.y); }
__device__ __forceinline__ float2 cml(float2 a, float2 b){
    return make_float2(fmaf(a.x,b.x,-a.y*b.y), fmaf(a.x,b.y, a.y*b.x));
}
__device__ __forceinline__ float2 cmlcj(float2 a, float2 b){ // a * conj(b)
    return make_float2(fmaf(a.x,b.x, a.y*b.y), fmaf(a.y,b.x,-a.x*b.y));
}

template<int DIR>
__device__ __forceinline__ float2 tw(const float2* W, int idx){
    float2 w = W[idx];
    return (DIR > 0) ? w : make_float2(w.x, -w.y);
}

// ---------------- Stockham radix-4 stage ----------------
// src stride-s layout: src[q + s*(p + m*r)]  ->  dst[q + s*(4p + r)] * w_n^{p r},
// with twiddle index = s*p*r in the global 320 table (s*n == 320 invariant).
template<int SS, int MM, int DIR>
__device__ __forceinline__ void stage_r4(const float2* src, float2* dst, const float2* W, int u){
    int p = u / SS;
    int q = u - p * SS;
    float2 a0 = src[q + SS*p];
    float2 a1 = src[q + SS*(p + MM)];
    float2 a2 = src[q + SS*(p + 2*MM)];
    float2 a3 = src[q + SS*(p + 3*MM)];
    float2 t0 = cad(a0,a2), t1 = csb(a0,a2), t2 = cad(a1,a3), t3 = csb(a1,a3);
    float2 b0 = cad(t0,t2), b2 = csb(t0,t2);
    float2 b1, b3;
    if (DIR > 0){
        b1 = make_float2(t1.x + t3.y, t1.y - t3.x);
        b3 = make_float2(t1.x - t3.y, t1.y + t3.x);
    } else {
        b1 = make_float2(t1.x - t3.y, t1.y + t3.x);
        b3 = make_float2(t1.x + t3.y, t1.y - t3.x);
    }
    int base = q + SS*4*p;
    dst[base]        = b0;
    dst[base +   SS] = cml(b1, tw<DIR>(W,     SS*p));
    dst[base + 2*SS] = cml(b2, tw<DIR>(W, 2 * SS*p));
    dst[base + 3*SS] = cml(b3, tw<DIR>(W, 3 * SS*p));
}

// ---------------- 320-point FFT, 80 threads (u in [0,80)) ----------------
// Factors 5,4,4,4. A -> B -> A -> B -> A. Natural order in and out. Unnormalized.
template<int DIR>
__device__ __forceinline__ void fft320(float2* A, float2* B, const float2* W, int u){
    if (u < 64){
        float2 a0=A[u], a1=A[u+64], a2=A[u+128], a3=A[u+192], a4=A[u+256];
        const float C1 =  0.3090169943749474241f;
        const float C2 = -0.8090169943749474241f;
        const float S1 =  0.9510565162951535721f;
        const float S2 =  0.5877852522924731292f;
        float2 t1 = cad(a1,a4), t2 = cad(a2,a3), t3 = csb(a1,a4), t4 = csb(a2,a3);
        float2 b0 = make_float2(a0.x + t1.x + t2.x, a0.y + t1.y + t2.y);
        float2 m1 = make_float2(fmaf(C1,t1.x, fmaf(C2,t2.x, a0.x)),
                                fmaf(C1,t1.y, fmaf(C2,t2.y, a0.y)));
        float2 m2 = make_float2(fmaf(C2,t1.x, fmaf(C1,t2.x, a0.x)),
                                fmaf(C2,t1.y, fmaf(C1,t2.y, a0.y)));
        float2 w1 = make_float2(fmaf(S1,t3.x,  S2*t4.x), fmaf(S1,t3.y,  S2*t4.y));
        float2 w2 = make_float2(fmaf(S2,t3.x, -S1*t4.x), fmaf(S2,t3.y, -S1*t4.y));
        float2 b1,b2,b3,b4;
        if (DIR > 0){
            b1 = make_float2(m1.x + w1.y, m1.y - w1.x);
            b4 = make_float2(m1.x - w1.y, m1.y + w1.x);
            b2 = make_float2(m2.x + w2.y, m2.y - w2.x);
            b3 = make_float2(m2.x - w2.y, m2.y + w2.x);
        } else {
            b1 = make_float2(m1.x - w1.y, m1.y + w1.x);
            b4 = make_float2(m1.x + w1.y, m1.y - w1.x);
            b2 = make_float2(m2.x - w2.y, m2.y + w2.x);
            b3 = make_float2(m2.x + w2.y, m2.y - w2.x);
        }
        B[5*u]   = b0;
        B[5*u+1] = cml(b1, tw<DIR>(W,   u));
        B[5*u+2] = cml(b2, tw<DIR>(W, 2*u));
        B[5*u+3] = cml(b3, tw<DIR>(W, 3*u));
        B[5*u+4] = cml(b4, tw<DIR>(W, 4*u));
    }
    __syncthreads();
    stage_r4<5,16,DIR>(B, A, W, u);  __syncthreads();
    stage_r4<20,4,DIR>(A, B, W, u);  __syncthreads();
    stage_r4<80,1,DIR>(B, A, W, u);  __syncthreads();
}

// ---------------- 320-thread block reduce -> part[bid] ----------------
__device__ __forceinline__ void reduce320(float v, float* part){
    __shared__ float rb[10];
    int tid = threadIdx.x;
    #pragma unroll
    for (int o = 16; o > 0; o >>= 1) v += __shfl_down_sync(0xffffffffu, v, o);
    if ((tid & 31) == 0) rb[tid >> 5] = v;
    __syncthreads();
    if (tid == 0){
        float t = 0.f;
        #pragma unroll
        for (int i = 0; i < 10; i++) t += rb[i];
        part[blockIdx.x] = t;
    }
}

// ---------------- init: twiddles ----------------
__global__ void k_init_tw(){
    int k = threadIdx.x;
    double a = -2.0 * 3.14159265358979323846 * (double)k / 320.0;
    d_W[k] = make_float2((float)cos(a), (float)sin(a));
}

// ---------------- K1: forward row FFT of csm*p, ishift folded ----------------
// grid 5120 (64 images x 80), block 320 = 4 rows x 80 fft-threads
__global__ void __launch_bounds__(320) k_fwd_row(const float2* __restrict__ csm,
                                                 const float2* __restrict__ pin){
    __shared__ float2 Ash[4][321], Bsh[4][321], Wsh[NN];
    int tid = threadIdx.x, lane = tid / 80, u = tid % 80;
    Wsh[tid] = d_W[tid];
    int bid = blockIdx.x;
    int g  = bid / 80;            // s*16 + c
    int h0 = (bid % 80) * 4;
    int s = g >> 4, c = g & 15;
    int wi = tid + HN; if (wi >= NN) wi -= NN;
    #pragma unroll
    for (int k = 0; k < 4; k++){
        int h = h0 + k;
        int hi = h + HN; if (hi >= NN) hi -= NN;
        float2 cv = csm[(c*NN + hi)*NN + wi];
        float2 pv = pin[(s*NN + hi)*NN + wi];
        Ash[k][tid] = cml(cv, pv);
    }
    __syncthreads();
    fft320<1>(Ash[lane], Bsh[lane], Wsh, u);
    int wo = tid + HN; if (wo >= NN) wo -= NN;
    #pragma unroll
    for (int k = 0; k < 4; k++)
        d_scr[(g*NN + h0 + k)*NN + wo] = Ash[k][tid];
}

// ---------------- K2: fused column fwd FFT + mask (+scale) + column inv FFT ----------------
// grid 5120 (64 images x 80), block 320 = 4 adjacent columns
__global__ void __launch_bounds__(320) k_col_ata(const float* __restrict__ mask, float mscale){
    __shared__ float2 Ash[4][321], Bsh[4][321], Wsh[NN];
    __shared__ float  Msh[4][320];
    int tid = threadIdx.x, lane = tid / 80, u = tid % 80;
    Wsh[tid] = d_W[tid];
    int bid = blockIdx.x;
    int g = bid / 80;
    int cw0 = (bid % 80) * 4;
    int s = g >> 4;
    int cc = tid & 3, hh = tid >> 2;
    #pragma unroll
    for (int k = 0; k < 4; k++){
        int h = hh + 80*k;
        Ash[cc][h] = d_scr[(g*NN + h)*NN + cw0 + cc];
        int hr = h + HN; if (hr >= NN) hr -= NN;
        Msh[cc][h] = mask[(s*NN + hr)*NN + cw0 + cc] * mscale;
    }
    __syncthreads();
    fft320<1>(Ash[lane], Bsh[lane], Wsh, u);
    #pragma unroll
    for (int k = 0; k < 4; k++){
        int j = u + 80*k;
        float m = Msh[lane][j];
        float2 v = Ash[lane][j];
        Ash[lane][j] = make_float2(v.x*m, v.y*m);
    }
    __syncthreads();
    fft320<-1>(Ash[lane], Bsh[lane], Wsh, u);
    #pragma unroll
    for (int k = 0; k < 4; k++){
        int h = hh + 80*k;
        d_scr[(g*NN + h)*NN + cw0 + cc] = Ash[cc][h];
    }
}

// ---------------- K2b: RHS column inverse FFT of mask*kdata (ishift folded) ----------------
__global__ void __launch_bounds__(320) k_col_rhs(const float2* __restrict__ kd,
                                                 const float* __restrict__ mask, float mscale){
    __shared__ float2 Ash[4][321], Bsh[4][321], Wsh[NN];
    int tid = threadIdx.x, lane = tid / 80, u = tid % 80;
    Wsh[tid] = d_W[tid];
    int bid = blockIdx.x;
    int g = bid / 80;
    int cw0 = (bid % 80) * 4;
    int s = g >> 4;
    int cc = tid & 3, hh = tid >> 2;
    #pragma unroll
    for (int k = 0; k < 4; k++){
        int j = hh + 80*k;
        int hr = j + HN; if (hr >= NN) hr -= NN;
        float  m = mask[(s*NN + hr)*NN + cw0 + cc] * mscale;
        float2 v = kd[(g*NN + hr)*NN + cw0 + cc];
        Ash[cc][j] = make_float2(v.x*m, v.y*m);
    }
    __syncthreads();
    fft320<-1>(Ash[lane], Bsh[lane], Wsh, u);
    #pragma unroll
    for (int k = 0; k < 4; k++){
        int h = hh + 80*k;
        d_scr[(g*NN + h)*NN + cw0 + cc] = Ash[cc][h];
    }
}

// ---------------- K3: inverse row FFT + coil combine + rho*z + partial dot ----------------
// grid 1280 (4 shots x 320 rows), block 320 = 4 coils per pass x 4 passes
__global__ void __launch_bounds__(320) k_inv_row(const float2* __restrict__ csm,
                                                 const float2* __restrict__ z,
                                                 float2* __restrict__ out,
                                                 float* __restrict__ part,
                                                 int dotMode){
    __shared__ float2 Ash[4][321], Bsh[4][321], Wsh[NN];
    int tid = threadIdx.x, lane = tid / 80, u = tid % 80;
    Wsh[tid] = d_W[tid];
    int bid = blockIdx.x;
    int s  = bid / NN;
    int hp = bid % NN;
    int hf = hp + HN; if (hf >= NN) hf -= NN;
    int wi = tid + HN; if (wi >= NN) wi -= NN;
    float2 acc = make_float2(0.f, 0.f);
    for (int it = 0; it < 4; ++it){
        __syncthreads();
        #pragma unroll
        for (int k = 0; k < 4; k++){
            int g = s*16 + (k + 4*it);
            Ash[k][tid] = d_scr[(g*NN + hp)*NN + wi];
        }
        __syncthreads();
        fft320<-1>(Ash[lane], Bsh[lane], Wsh, u);
        #pragma unroll
        for (int k = 0; k < 4; k++){
            int c = k + 4*it;
            float2 v  = Ash[k][wi];
            float2 sc = csm[(c*NN + hf)*NN + tid];
            acc = cad(acc, cmlcj(v, sc));
        }
    }
    int oi = (s*NN + hf)*NN + tid;
    float2 zv = z[oi];
    float2 o  = make_float2(fmaf(RHO_F, zv.x, acc.x), fmaf(RHO_F, zv.y, acc.y));
    out[oi] = o;
    float dv = dotMode ? (o.x*o.x + o.y*o.y) : (zv.x*o.x + zv.y*o.y);
    reduce320(dv, part);
}

// ---------------- deterministic finalize of partials ----------------
// mode 0: rs = sum ; mode 1: alpha = rs/(pAp+eps) ; mode 2: beta = rsnew/(rs+eps), rs = rsnew
__global__ void __launch_bounds__(1024) k_fin(const float* __restrict__ part, int n, int mode){
    __shared__ float sb[1024];
    int tid = threadIdx.x;
    float v = 0.f;
    for (int i = tid; i < n; i += 1024) v += part[i];
    sb[tid] = v; __syncthreads();
    #pragma unroll
    for (int st = 512; st > 0; st >>= 1){
        if (tid < st) sb[tid] += sb[tid + st];
        __syncthreads();
    }
    if (tid == 0){
        float t = sb[0];
        if      (mode == 0) d_sc[0] = t;
        else if (mode == 1) d_sc[1] = d_sc[0] / (t + EPS_F);
        else               { d_sc[2] = t / (d_sc[0] + EPS_F); d_sc[0] = t; }
    }
}

// ---------------- CG vector updates ----------------
__global__ void __launch_bounds__(256) k_init_vec(){
    int i = blockIdx.x*256 + threadIdx.x;
    d_x[i] = make_float2(0.f, 0.f);
    d_p[i] = d_r[i];
}
__global__ void __launch_bounds__(256) k_axpy(float* __restrict__ part){
    int i = blockIdx.x*256 + threadIdx.x;
    float alpha = d_sc[1];
    float2 pv = d_p[i], av = d_Ap[i];
    float2 xv = d_x[i];
    xv.x = fmaf(alpha, pv.x, xv.x); xv.y = fmaf(alpha, pv.y, xv.y);
    d_x[i] = xv;
    float2 rv = d_r[i];
    rv.x = fmaf(-alpha, av.x, rv.x); rv.y = fmaf(-alpha, av.y, rv.y);
    d_r[i] = rv;
    float dv = rv.x*rv.x + rv.y*rv.y;
    // 256-thread block reduce
    __shared__ float rb[8];
    int tid = threadIdx.x;
    #pragma unroll
    for (int o = 16; o > 0; o >>= 1) dv += __shfl_down_sync(0xffffffffu, dv, o);
    if ((tid & 31) == 0) rb[tid >> 5] = dv;
    __syncthreads();
    if (tid == 0){
        float t = 0.f;
        #pragma unroll
        for (int k = 0; k < 8; k++) t += rb[k];
        part[blockIdx.x] = t;
    }
}
__global__ void __launch_bounds__(256) k_updp(){
    int i = blockIdx.x*256 + threadIdx.x;
    float beta = d_sc[2];
    float2 rv = d_r[i], pv = d_p[i];
    d_p[i] = make_float2(fmaf(beta, pv.x, rv.x), fmaf(beta, pv.y, rv.y));
}
__global__ void __launch_bounds__(256) k_out(float2* __restrict__ o){
    int i = blockIdx.x*256 + threadIdx.x;
    o[i] = d_x[i];
}

// ---------------- launch ----------------
extern "C" void kernel_launch(void* const* d_in, const int* in_sizes, int n_in,
                              void* d_out, int out_size){
    const float2* kd = nullptr;
    const float2* I  = nullptr;
    const float2* csm = nullptr;
    const float*  mask = nullptr;
    for (int i = 0; i < n_in; i++){
        int sz = in_sizes[i];
        if      (sz == 13107200) kd   = (const float2*)d_in[i];
        else if (sz == 819200)   I    = (const float2*)d_in[i];
        else if (sz == 3276800)  csm  = (const float2*)d_in[i];
        else if (sz == 409600)   mask = (const float*) d_in[i];
    }

    float2 *rp, *pp, *App;
    float  *part;
    cudaGetSymbolAddress((void**)&rp,   d_r);
    cudaGetSymbolAddress((void**)&pp,   d_p);
    cudaGetSymbolAddress((void**)&App,  d_Ap);
    cudaGetSymbolAddress((void**)&part, d_part);

    const float invN  = 1.0f / 320.0f;            // ortho inverse (rhs)
    const float invN2 = 1.0f / (320.0f * 320.0f); // fwd*inv ortho (AtA)

    k_init_tw<<<1, 320>>>();

    // rhs = EH(kdata) + rho*I  -> r ; rs0 = |r|^2 ; x = 0 ; p = r
    k_col_rhs<<<5120, 320>>>(kd, mask, invN);
    k_inv_row<<<1280, 320>>>(csm, I, rp, part, 1);
    k_fin<<<1, 1024>>>(part, 1280, 0);
    k_init_vec<<<1600, 256>>>();

    for (int it = 0; it < 15; ++it){
        k_fwd_row<<<5120, 320>>>(csm, pp);                 // scr = FFT_rows(csm*p)
        k_col_ata<<<5120, 320>>>(mask, invN2);             // scr = IFFT_cols(mask*FFT_cols(scr))
        k_inv_row<<<1280, 320>>>(csm, pp, App, part, 0);   // Ap = coilsum + rho*p ; part = p.Ap
        k_fin<<<1, 1024>>>(part, 1280, 1);                 // alpha
        k_axpy<<<1600, 256>>>(part);                       // x,r update ; part = |r|^2
        k_fin<<<1, 1024>>>(part, 1600, 2);                 // beta, rs
        k_updp<<<1600, 256>>>();                           // p = r + beta*p
    }

    k_out<<<1600, 256>>>((float2*)d_out);
    (void)out_size;
}